// round 14
// baseline (speedup 1.0000x reference)
#include <cuda_runtime.h>
#include <cuda_bf16.h>

// BoxFilter r=8 (k=17), separable, zero padding, fused.
// 256-thread CTA, 64x64 tile, two 32-col halves, phase-merged:
//   fill -> B0(160) -> [B1(160) || C0a(96)] -> [C0b(32) || C1(128)]
// s_h is pitch-32 with a 4-float row-rotation swizzle; B1's h-sums go into
// s_in's dead cols 0..31 (same swizzle). Smem 37.1 KB -> 6 CTAs/SM.
// Phase C: strength-reduced swizzle addressing (8 base pointers, rotation
// period 8) + FFMA-folded scale in the sliding window.
// Input x: [8, 32, 512, 512] f32 (256 images of 512x512), same-shape output.

#define RAD 8
#define KW  (2 * RAD + 1)          // 17
#define TILE_W 64
#define TILE_H 64
#define IN_W  (TILE_W + 2 * RAD)   // 80
#define IN_H  (TILE_H + 2 * RAD)   // 80
#define IN_PITCH 84                // 21x16B rows -> conflict-free LDS.128
#define HALF_W 32
#define HS_PITCH 32                // swizzled (row-rotated) -> conflict-free
#define NTHREADS 256

// Horizontal running sums for one half-tile task (row, strip in {0,1}).
__device__ __forceinline__ void phase_b(const float* s_in, float* buf,
                                        int pitch, int cin, int t) {
    const int row = (t < IN_H) ? t : t - IN_H;
    const int stp16 = (t < IN_H) ? 0 : 16;

    const float* p = &s_in[row * IN_PITCH + cin + stp16];
    float v[32];
    #pragma unroll
    for (int j = 0; j < 8; j++) {
        float4 q4 = *reinterpret_cast<const float4*>(p + 4 * j);
        v[4*j + 0] = q4.x; v[4*j + 1] = q4.y;
        v[4*j + 2] = q4.z; v[4*j + 3] = q4.w;
    }

    float h[16];
    float sum = 0.0f;
    #pragma unroll
    for (int j = 0; j < KW; j++) sum += v[j];
    h[0] = sum;
    #pragma unroll
    for (int c = 1; c < 16; c++) {
        sum += v[c + KW - 1] - v[c - 1];
        h[c] = sum;
    }

    // swizzled write: physical col = (logical col + 4*(row&7)) & 31
    const int rot = (row & 7) * 4;
    float* rp = &buf[row * pitch];
    #pragma unroll
    for (int k = 0; k < 4; k++) {
        const int off = (stp16 + 4 * k + rot) & 31;
        *reinterpret_cast<float4*>(rp + off) =
            make_float4(h[4*k], h[4*k+1], h[4*k+2], h[4*k+3]);
    }
}

// Vertical running sums + streaming store for one 16-row segment of one
// half-tile column. Swizzle rotation has period 8 and r0 % 16 == 0, so rows
// j and j+8 share a physical column: 8 base pointers + immediate offsets.
__device__ __forceinline__ void phase_c(const float* buf, int pitch,
                                        float* __restrict__ dst,
                                        int x0, int y0, int c_base,
                                        int col, int r0, int W) {
    const float scale = 1.0f / ((float)KW * (float)KW);

    const float* bp[8];
    #pragma unroll
    for (int k = 0; k < 8; k++)
        bp[k] = &buf[(r0 + k) * pitch + ((col + 4 * k) & 31)];

    float v[32];
    #pragma unroll
    for (int j = 0; j < 32; j++)
        v[j] = bp[j & 7][(j >> 3) * 8 * pitch];   // immediate offsets

    float* p = dst + (size_t)(y0 + r0) * W + (x0 + c_base + col);

    float sum = 0.0f;
    #pragma unroll
    for (int j = 0; j < KW; j++) sum += v[j];
    float o = sum * scale;                         // scaled running value
    __stcs(p, o);

    #pragma unroll
    for (int i = 1; i < 16; i++) {
        o = fmaf(v[i + KW - 1] - v[i - 1], scale, o);
        p += W;
        __stcs(p, o);
    }
}

__global__ __launch_bounds__(NTHREADS, 6)
void box_filter_fused(const float* __restrict__ in, float* __restrict__ out,
                      int H, int W) {
    __shared__ float s_in[IN_H * IN_PITCH];   // 80*84*4 = 26,880 B
    __shared__ float s_h [IN_H * HS_PITCH];   // 80*32*4 = 10,240 B (37.1 KB total)

    const int bx  = blockIdx.x;
    const int img = blockIdx.z;
    const int x0  = bx * TILE_W;
    const int y0  = blockIdx.y * TILE_H;
    const int tid = threadIdx.x;

    const float* __restrict__ src = in + (size_t)img * H * W;
    float* __restrict__ dst = out + (size_t)img * H * W;

    // ---- Phase A: cp.async tile load (80 rows x 20 float4), zero-filled OOB ----
    {
        const bool interior_x = (bx > 0) && (bx < (W / TILE_W) - 1);
        const int wlim = W - 4;
        int r = tid / 20;
        int q = tid - r * 20;
        #pragma unroll
        for (int it = 0; it < 7; it++) {
            const int idx = tid + it * NTHREADS;
            if (idx < IN_H * 20) {
                const int gy = y0 - RAD + r;
                const int gx = x0 - RAD + 4 * q;
                const bool ok = ((unsigned)gy < (unsigned)H) &&
                                (interior_x || (unsigned)gx <= (unsigned)wlim);
                const float* gptr = src + (ok ? ((size_t)gy * W + gx) : 0);
                unsigned saddr = (unsigned)__cvta_generic_to_shared(&s_in[r * IN_PITCH + 4 * q]);
                const int sz = ok ? 16 : 0;  // src-size 0 -> zero fill
                asm volatile("cp.async.cg.shared.global [%0], [%1], 16, %2;\n"
                             :: "r"(saddr), "l"(gptr), "r"(sz));
            }
            r += 12; q += 16;
            if (q >= 20) { q -= 20; r += 1; }
        }
    }
    asm volatile("cp.async.commit_group;\n" ::: "memory");
    asm volatile("cp.async.wait_group 0;\n" ::: "memory");
    __syncthreads();

    // ---- B0: h-sums for half 0 (reads s_in cols 0..47) -> s_h (swizzled) ----
    if (tid < IN_H * 2)
        phase_b(s_in, s_h, HS_PITCH, 0, tid);
    __syncthreads();

    // ---- Merged: B1 (thr 0..159) || C0a (thr 160..255, segs 0..2) ----
    if (tid < IN_H * 2) {
        phase_b(s_in, s_in, IN_PITCH, HALF_W, tid);
    } else {
        const int t2 = tid - IN_H * 2;          // 0..95
        phase_c(s_h, HS_PITCH, dst, x0, y0, 0, t2 & 31, (t2 >> 5) << 4, W);
    }
    __syncthreads();

    // ---- Final: C0b (thr 0..31, seg 3) || C1 (thr 32..159, segs 0..3) ----
    if (tid < 32) {
        phase_c(s_h, HS_PITCH, dst, x0, y0, 0, tid, 48, W);
    } else if (tid < 160) {
        const int t3 = tid - 32;                // 0..127
        phase_c(s_in, IN_PITCH, dst, x0, y0, HALF_W, t3 & 31, (t3 >> 5) << 4, W);
    }
}

extern "C" void kernel_launch(void* const* d_in, const int* in_sizes, int n_in,
                              void* d_out, int out_size) {
    const float* x = (const float*)d_in[0];
    float* out = (float*)d_out;

    const int N = 8, C = 32, H = 512, W = 512;
    (void)in_sizes; (void)n_in; (void)out_size;

    dim3 grid(W / TILE_W, H / TILE_H, N * C);  // 8 x 8 x 256 = 16384 blocks
    box_filter_fused<<<grid, NTHREADS>>>(x, out, H, W);
}

// round 15
// speedup vs baseline: 1.0088x; 1.0088x over previous
#include <cuda_runtime.h>
#include <cuda_bf16.h>

// BoxFilter r=8 (k=17), separable, zero padding, fused.
// 256-thread CTA, 64x64 tile, two 32-col halves, phase-merged:
//   fill -> B0(160) -> [B1(160) || C0a(96)] -> [C0b(32) || C1(128)]
// s_h is pitch-32 with a 4-float row-rotation swizzle; B1's h-sums go into
// s_in's dead cols 0..31 (same swizzle). Smem 37.1 KB -> 6 CTAs/SM.
// Phase C: R13's independent per-load swizzle addressing (max MLP) +
// FFMA-folded scale in the sliding window (2 FP/output).
// Input x: [8, 32, 512, 512] f32 (256 images of 512x512), same-shape output.

#define RAD 8
#define KW  (2 * RAD + 1)          // 17
#define TILE_W 64
#define TILE_H 64
#define IN_W  (TILE_W + 2 * RAD)   // 80
#define IN_H  (TILE_H + 2 * RAD)   // 80
#define IN_PITCH 84                // 21x16B rows -> conflict-free LDS.128
#define HALF_W 32
#define HS_PITCH 32                // swizzled (row-rotated) -> conflict-free
#define NTHREADS 256

// Horizontal running sums for one half-tile task (row, strip in {0,1}).
__device__ __forceinline__ void phase_b(const float* s_in, float* buf,
                                        int pitch, int cin, int t) {
    const int row = (t < IN_H) ? t : t - IN_H;
    const int stp16 = (t < IN_H) ? 0 : 16;

    const float* p = &s_in[row * IN_PITCH + cin + stp16];
    float v[32];
    #pragma unroll
    for (int j = 0; j < 8; j++) {
        float4 q4 = *reinterpret_cast<const float4*>(p + 4 * j);
        v[4*j + 0] = q4.x; v[4*j + 1] = q4.y;
        v[4*j + 2] = q4.z; v[4*j + 3] = q4.w;
    }

    float h[16];
    float sum = 0.0f;
    #pragma unroll
    for (int j = 0; j < KW; j++) sum += v[j];
    h[0] = sum;
    #pragma unroll
    for (int c = 1; c < 16; c++) {
        sum += v[c + KW - 1] - v[c - 1];
        h[c] = sum;
    }

    // swizzled write: physical col = (logical col + 4*(row&7)) & 31
    const int rot = (row & 7) * 4;
    float* rp = &buf[row * pitch];
    #pragma unroll
    for (int k = 0; k < 4; k++) {
        const int off = (stp16 + 4 * k + rot) & 31;
        *reinterpret_cast<float4*>(rp + off) =
            make_float4(h[4*k], h[4*k+1], h[4*k+2], h[4*k+3]);
    }
}

// Vertical running sums + streaming store for one 16-row segment of one
// half-tile column. Independent swizzled address per load (max MLP).
__device__ __forceinline__ void phase_c(const float* buf, int pitch,
                                        float* __restrict__ dst,
                                        int x0, int y0, int c_base,
                                        int col, int r0, int W) {
    const float scale = 1.0f / ((float)KW * (float)KW);

    const float* rowp = &buf[r0 * pitch];
    float v[32];
    #pragma unroll
    for (int j = 0; j < 32; j++) {
        const int pc = (col + ((j & 7) << 2)) & 31;  // r0 % 8 == 0
        v[j] = rowp[j * pitch + pc];
    }

    float* p = dst + (size_t)(y0 + r0) * W + (x0 + c_base + col);

    float sum = 0.0f;
    #pragma unroll
    for (int j = 0; j < KW; j++) sum += v[j];
    float o = sum * scale;                 // scaled running value
    __stcs(p, o);

    #pragma unroll
    for (int i = 1; i < 16; i++) {
        o = fmaf(v[i + KW - 1] - v[i - 1], scale, o);
        p += W;
        __stcs(p, o);
    }
}

__global__ __launch_bounds__(NTHREADS, 6)
void box_filter_fused(const float* __restrict__ in, float* __restrict__ out,
                      int H, int W) {
    __shared__ float s_in[IN_H * IN_PITCH];   // 80*84*4 = 26,880 B
    __shared__ float s_h [IN_H * HS_PITCH];   // 80*32*4 = 10,240 B (37.1 KB total)

    const int bx  = blockIdx.x;
    const int img = blockIdx.z;
    const int x0  = bx * TILE_W;
    const int y0  = blockIdx.y * TILE_H;
    const int tid = threadIdx.x;

    const float* __restrict__ src = in + (size_t)img * H * W;
    float* __restrict__ dst = out + (size_t)img * H * W;

    // ---- Phase A: cp.async tile load (80 rows x 20 float4), zero-filled OOB ----
    {
        const bool interior_x = (bx > 0) && (bx < (W / TILE_W) - 1);
        const int wlim = W - 4;
        int r = tid / 20;
        int q = tid - r * 20;
        #pragma unroll
        for (int it = 0; it < 7; it++) {
            const int idx = tid + it * NTHREADS;
            if (idx < IN_H * 20) {
                const int gy = y0 - RAD + r;
                const int gx = x0 - RAD + 4 * q;
                const bool ok = ((unsigned)gy < (unsigned)H) &&
                                (interior_x || (unsigned)gx <= (unsigned)wlim);
                const float* gptr = src + (ok ? ((size_t)gy * W + gx) : 0);
                unsigned saddr = (unsigned)__cvta_generic_to_shared(&s_in[r * IN_PITCH + 4 * q]);
                const int sz = ok ? 16 : 0;  // src-size 0 -> zero fill
                asm volatile("cp.async.cg.shared.global [%0], [%1], 16, %2;\n"
                             :: "r"(saddr), "l"(gptr), "r"(sz));
            }
            r += 12; q += 16;
            if (q >= 20) { q -= 20; r += 1; }
        }
    }
    asm volatile("cp.async.commit_group;\n" ::: "memory");
    asm volatile("cp.async.wait_group 0;\n" ::: "memory");
    __syncthreads();

    // ---- B0: h-sums for half 0 (reads s_in cols 0..47) -> s_h (swizzled) ----
    if (tid < IN_H * 2)
        phase_b(s_in, s_h, HS_PITCH, 0, tid);
    __syncthreads();

    // ---- Merged: B1 (thr 0..159) || C0a (thr 160..255, segs 0..2) ----
    if (tid < IN_H * 2) {
        phase_b(s_in, s_in, IN_PITCH, HALF_W, tid);
    } else {
        const int t2 = tid - IN_H * 2;          // 0..95
        phase_c(s_h, HS_PITCH, dst, x0, y0, 0, t2 & 31, (t2 >> 5) << 4, W);
    }
    __syncthreads();

    // ---- Final: C0b (thr 0..31, seg 3) || C1 (thr 32..159, segs 0..3) ----
    if (tid < 32) {
        phase_c(s_h, HS_PITCH, dst, x0, y0, 0, tid, 48, W);
    } else if (tid < 160) {
        const int t3 = tid - 32;                // 0..127
        phase_c(s_in, IN_PITCH, dst, x0, y0, HALF_W, t3 & 31, (t3 >> 5) << 4, W);
    }
}

extern "C" void kernel_launch(void* const* d_in, const int* in_sizes, int n_in,
                              void* d_out, int out_size) {
    const float* x = (const float*)d_in[0];
    float* out = (float*)d_out;

    const int N = 8, C = 32, H = 512, W = 512;
    (void)in_sizes; (void)n_in; (void)out_size;

    dim3 grid(W / TILE_W, H / TILE_H, N * C);  // 8 x 8 x 256 = 16384 blocks
    box_filter_fused<<<grid, NTHREADS>>>(x, out, H, W);
}

// round 16
// speedup vs baseline: 1.0106x; 1.0018x over previous
#include <cuda_runtime.h>
#include <cuda_bf16.h>

// BoxFilter r=8 (k=17), separable, zero padding, fused.
// 256-thread CTA, 64x64 tile, two 32-col halves, phase-merged:
//   fill -> B0(160) -> [B1(160) || C0a(96)] -> [C0b(32) || C1(128)]
// Half 0: h-sums stored TRANSPOSED (s_hT[c][row], pitch 81) -> B0 writes are
// stride-1 across lanes, C0 reads are one base + 32 immediate-offset LDS.32,
// both conflict-free, zero swizzle ALU.
// Half 1: h-sums in s_in's dead cols 0..31 with row-rotation swizzle (R13).
// Smem 37,248 B -> 6 CTAs/SM. FFMA-folded scale in all C slides.
// Input x: [8, 32, 512, 512] f32 (256 images of 512x512), same-shape output.

#define RAD 8
#define KW  (2 * RAD + 1)          // 17
#define TILE_W 64
#define TILE_H 64
#define IN_W  (TILE_W + 2 * RAD)   // 80
#define IN_H  (TILE_H + 2 * RAD)   // 80
#define IN_PITCH 84                // 21x16B rows -> conflict-free LDS.128
#define HALF_W 32
#define HT_PITCH 81                // transposed h-buffer pitch (odd -> CF)
#define NTHREADS 256

// ---- Half 0: horizontal running sums, TRANSPOSED store ----
// Task t (0..159): row = t%80, h-col strip stp16 in {0,16}.
// Writes h(row, stp16+c) to s_hT[(stp16+c)*HT_PITCH + row], c = 0..15.
__device__ __forceinline__ void phase_b0T(const float* s_in, float* hT, int t) {
    const int row   = (t < IN_H) ? t : t - IN_H;
    const int stp16 = (t < IN_H) ? 0 : 16;

    const float* p = &s_in[row * IN_PITCH + stp16];
    float v[32];
    #pragma unroll
    for (int j = 0; j < 8; j++) {
        float4 q4 = *reinterpret_cast<const float4*>(p + 4 * j);
        v[4*j + 0] = q4.x; v[4*j + 1] = q4.y;
        v[4*j + 2] = q4.z; v[4*j + 3] = q4.w;
    }

    float* wp = &hT[stp16 * HT_PITCH + row];   // one base, immediate steps
    float sum = 0.0f;
    #pragma unroll
    for (int j = 0; j < KW; j++) sum += v[j];
    wp[0] = sum;
    #pragma unroll
    for (int c = 1; c < 16; c++) {
        sum += v[c + KW - 1] - v[c - 1];
        wp[c * HT_PITCH] = sum;
    }
}

// ---- Half 0: vertical running sums from transposed buffer + store ----
__device__ __forceinline__ void phase_c0T(const float* hT,
                                          float* __restrict__ dst,
                                          int x0, int y0,
                                          int col, int r0, int W) {
    const float scale = 1.0f / ((float)KW * (float)KW);

    const float* rp = &hT[col * HT_PITCH + r0];  // one IMAD, then immediates
    float v[32];
    #pragma unroll
    for (int j = 0; j < 32; j++)
        v[j] = rp[j];

    float* p = dst + (size_t)(y0 + r0) * W + (x0 + col);

    float sum = 0.0f;
    #pragma unroll
    for (int j = 0; j < KW; j++) sum += v[j];
    float o = sum * scale;
    __stcs(p, o);

    #pragma unroll
    for (int i = 1; i < 16; i++) {
        o = fmaf(v[i + KW - 1] - v[i - 1], scale, o);
        p += W;
        __stcs(p, o);
    }
}

// ---- Half 1: horizontal running sums into dead s_in cols (swizzled) ----
__device__ __forceinline__ void phase_b1(const float* s_in, float* buf, int t) {
    const int row   = (t < IN_H) ? t : t - IN_H;
    const int stp16 = (t < IN_H) ? 0 : 16;

    const float* p = &s_in[row * IN_PITCH + HALF_W + stp16];
    float v[32];
    #pragma unroll
    for (int j = 0; j < 8; j++) {
        float4 q4 = *reinterpret_cast<const float4*>(p + 4 * j);
        v[4*j + 0] = q4.x; v[4*j + 1] = q4.y;
        v[4*j + 2] = q4.z; v[4*j + 3] = q4.w;
    }

    float h[16];
    float sum = 0.0f;
    #pragma unroll
    for (int j = 0; j < KW; j++) sum += v[j];
    h[0] = sum;
    #pragma unroll
    for (int c = 1; c < 16; c++) {
        sum += v[c + KW - 1] - v[c - 1];
        h[c] = sum;
    }

    // swizzled write: physical col = (logical col + 4*(row&7)) & 31
    const int rot = (row & 7) * 4;
    float* rp = &buf[row * IN_PITCH];
    #pragma unroll
    for (int k = 0; k < 4; k++) {
        const int off = (stp16 + 4 * k + rot) & 31;
        *reinterpret_cast<float4*>(rp + off) =
            make_float4(h[4*k], h[4*k+1], h[4*k+2], h[4*k+3]);
    }
}

// ---- Half 1: vertical running sums from swizzled dead-space buffer ----
__device__ __forceinline__ void phase_c1(const float* buf,
                                         float* __restrict__ dst,
                                         int x0, int y0,
                                         int col, int r0, int W) {
    const float scale = 1.0f / ((float)KW * (float)KW);

    const float* rowp = &buf[r0 * IN_PITCH];
    float v[32];
    #pragma unroll
    for (int j = 0; j < 32; j++) {
        const int pc = (col + ((j & 7) << 2)) & 31;  // r0 % 8 == 0
        v[j] = rowp[j * IN_PITCH + pc];
    }

    float* p = dst + (size_t)(y0 + r0) * W + (x0 + HALF_W + col);

    float sum = 0.0f;
    #pragma unroll
    for (int j = 0; j < KW; j++) sum += v[j];
    float o = sum * scale;
    __stcs(p, o);

    #pragma unroll
    for (int i = 1; i < 16; i++) {
        o = fmaf(v[i + KW - 1] - v[i - 1], scale, o);
        p += W;
        __stcs(p, o);
    }
}

__global__ __launch_bounds__(NTHREADS, 6)
void box_filter_fused(const float* __restrict__ in, float* __restrict__ out,
                      int H, int W) {
    __shared__ float s_in[IN_H * IN_PITCH];       // 80*84*4 = 26,880 B
    __shared__ float s_hT[HALF_W * HT_PITCH];     // 32*81*4 = 10,368 B (37,248 B)

    const int bx  = blockIdx.x;
    const int img = blockIdx.z;
    const int x0  = bx * TILE_W;
    const int y0  = blockIdx.y * TILE_H;
    const int tid = threadIdx.x;

    const float* __restrict__ src = in + (size_t)img * H * W;
    float* __restrict__ dst = out + (size_t)img * H * W;

    // ---- Phase A: cp.async tile load (80 rows x 20 float4), zero-filled OOB ----
    {
        const bool interior_x = (bx > 0) && (bx < (W / TILE_W) - 1);
        const int wlim = W - 4;
        int r = tid / 20;
        int q = tid - r * 20;
        #pragma unroll
        for (int it = 0; it < 7; it++) {
            const int idx = tid + it * NTHREADS;
            if (idx < IN_H * 20) {
                const int gy = y0 - RAD + r;
                const int gx = x0 - RAD + 4 * q;
                const bool ok = ((unsigned)gy < (unsigned)H) &&
                                (interior_x || (unsigned)gx <= (unsigned)wlim);
                const float* gptr = src + (ok ? ((size_t)gy * W + gx) : 0);
                unsigned saddr = (unsigned)__cvta_generic_to_shared(&s_in[r * IN_PITCH + 4 * q]);
                const int sz = ok ? 16 : 0;  // src-size 0 -> zero fill
                asm volatile("cp.async.cg.shared.global [%0], [%1], 16, %2;\n"
                             :: "r"(saddr), "l"(gptr), "r"(sz));
            }
            r += 12; q += 16;
            if (q >= 20) { q -= 20; r += 1; }
        }
    }
    asm volatile("cp.async.commit_group;\n" ::: "memory");
    asm volatile("cp.async.wait_group 0;\n" ::: "memory");
    __syncthreads();

    // ---- B0: transposed h-sums for half 0 (reads s_in cols 0..47) ----
    if (tid < IN_H * 2)
        phase_b0T(s_in, s_hT, tid);
    __syncthreads();

    // ---- Merged: B1 (thr 0..159) || C0a (thr 160..255, segs 0..2) ----
    // B1 reads s_in cols 32..79, writes swizzled h-sums into DEAD s_in cols
    // 0..31. C0a reads s_hT. All ranges disjoint.
    if (tid < IN_H * 2) {
        phase_b1(s_in, s_in, tid);
    } else {
        const int t2 = tid - IN_H * 2;          // 0..95
        phase_c0T(s_hT, dst, x0, y0, t2 & 31, (t2 >> 5) << 4, W);
    }
    __syncthreads();

    // ---- Final: C0b (thr 0..31, seg 3) || C1 (thr 32..159, segs 0..3) ----
    if (tid < 32) {
        phase_c0T(s_hT, dst, x0, y0, tid, 48, W);
    } else if (tid < 160) {
        const int t3 = tid - 32;                // 0..127
        phase_c1(s_in, dst, x0, y0, t3 & 31, (t3 >> 5) << 4, W);
    }
}

extern "C" void kernel_launch(void* const* d_in, const int* in_sizes, int n_in,
                              void* d_out, int out_size) {
    const float* x = (const float*)d_in[0];
    float* out = (float*)d_out;

    const int N = 8, C = 32, H = 512, W = 512;
    (void)in_sizes; (void)n_in; (void)out_size;

    dim3 grid(W / TILE_W, H / TILE_H, N * C);  // 8 x 8 x 256 = 16384 blocks
    box_filter_fused<<<grid, NTHREADS>>>(x, out, H, W);
}